// round 1
// baseline (speedup 1.0000x reference)
#include <cuda_runtime.h>
#include <math.h>

// ---------------- problem constants ----------------
#define BB   4
#define LLEN 4096
#define DD   768
#define KK   12
#define KQ   6
#define HH   64
#define MEM  768          // K*H
#define ZCW  780          // MEM + K
#define CHN  1548         // K + 2*FLAT
#define FLAT 768
#define DSW  384
#define DEXP 192
#define LAT  192
#define CKN  4
#define TOK  (BB*LLEN)    // 16384
#define NCH  32           // scan chunks per sequence
#define CLEN 128          // elements per chunk (NCH*CLEN = L)

// ---------------- device scratch ----------------
__device__ float g_z[TOK * ZCW];        //  51 MB : conv input z = x@W_mem
__device__ float g_q[TOK * 768];        //  50 MB : q projections
__device__ float g_merged[TOK * CHN];   // 101 MB : merged -> in-place cumsum
__device__ float g_part[BB * CHN * NCH];
__device__ float g_o[TOK * 1536];       // 100 MB : [o_re|o_im] per k
__device__ float g_glin[TOK * KK];
__device__ float g_lat[TOK * LAT];
__device__ float g_ydir[TOK * 4608];    // 302 MB : y_dir, then spec-fused result
__device__ float g_ya[TOK * 2304];      // 151 MB
__device__ float g_theta[768];
__device__ float g_slope[KK];

// ---------------- helpers ----------------
__device__ __forceinline__ float softplus_f(float x) {
    return (x > 0.f) ? x + log1pf(expf(-x)) : log1pf(expf(x));
}
__device__ __forceinline__ float sigmoid_f(float x) {
    return 1.f / (1.f + expf(-x));
}

// ---------------- precompute theta/slopes ----------------
__global__ void precomp_kernel(const float* __restrict__ theta_raw,
                               const float* __restrict__ decay_slopes) {
    int i = threadIdx.x;
    if (i < 768) g_theta[i] = softplus_f(theta_raw[i]) + 0.001f;
    if (i < KK)  g_slope[i] = softplus_f(decay_slopes[i]);
}

// ---------------- generic SGEMM: C[M,N] = A[M,K] * B[K,N] ----------------
// A row-major (lda), B row-major (ldb), C row-major (ldc).
// Requires: M % 128 == 0, K % 8 == 0, N % 4 == 0, all row strides % 4 == 0.
__global__ __launch_bounds__(256)
void sgemm128(const float* __restrict__ A, const float* __restrict__ B,
              float* __restrict__ C, int N, int Kd, int lda, int ldb, int ldc) {
    __shared__ float As[8][128];
    __shared__ float Bs[8][128];
    const int tid = threadIdx.x;
    const int tx = tid & 15;
    const int ty = tid >> 4;
    const int rowBase = blockIdx.y * 128;
    const int colBase = blockIdx.x * 128;

    const int arow = tid >> 1;
    const int acol = (tid & 1) << 2;
    const int brow = tid >> 5;
    const int bcol = (tid & 31) << 2;

    float acc[8][8];
#pragma unroll
    for (int i = 0; i < 8; i++)
#pragma unroll
        for (int j = 0; j < 8; j++) acc[i][j] = 0.f;

    const float* Ap = A + (size_t)(rowBase + arow) * lda + acol;
    const int gc = colBase + bcol;

    for (int k0 = 0; k0 < Kd; k0 += 8) {
        float4 av = *(const float4*)(Ap + k0);
        As[acol + 0][arow] = av.x;
        As[acol + 1][arow] = av.y;
        As[acol + 2][arow] = av.z;
        As[acol + 3][arow] = av.w;
        float4 bv = make_float4(0.f, 0.f, 0.f, 0.f);
        if (gc < N) bv = *(const float4*)(B + (size_t)(k0 + brow) * ldb + gc);
        *(float4*)&Bs[brow][bcol] = bv;
        __syncthreads();
#pragma unroll
        for (int kk = 0; kk < 8; kk++) {
            float ar[8], br[8];
            *(float4*)&ar[0] = *(const float4*)&As[kk][ty * 8];
            *(float4*)&ar[4] = *(const float4*)&As[kk][ty * 8 + 4];
            *(float4*)&br[0] = *(const float4*)&Bs[kk][tx * 8];
            *(float4*)&br[4] = *(const float4*)&Bs[kk][tx * 8 + 4];
#pragma unroll
            for (int i = 0; i < 8; i++)
#pragma unroll
                for (int j = 0; j < 8; j++) acc[i][j] += ar[i] * br[j];
        }
        __syncthreads();
    }
#pragma unroll
    for (int i = 0; i < 8; i++) {
        int r = rowBase + ty * 8 + i;
        float* Crow = C + (size_t)r * ldc;
#pragma unroll
        for (int j0 = 0; j0 < 8; j0 += 4) {
            int cc = colBase + tx * 8 + j0;
            if (cc < N) {
                float4 v = make_float4(acc[i][j0], acc[i][j0 + 1],
                                       acc[i][j0 + 2], acc[i][j0 + 3]);
                *(float4*)(Crow + cc) = v;
            }
        }
    }
}

// ---------------- conv + merged construction ----------------
// merged layout per token: [0,12) p_w ; [12,780) re_k ; [780,1548) im_k
__global__ __launch_bounds__(256)
void build_merged_kernel(const float* __restrict__ ck,
                         const float* __restrict__ score_scale) {
    const int t = blockIdx.x;
    const int l = t & (LLEN - 1);
    const int tid = threadIdx.x;
    __shared__ float spw[KK];
    const int tb = t * CHN;

    if (tid < KK) {
        float s = 0.f;
#pragma unroll
        for (int i = 0; i < CKN; i++) {
            int ll = l - (CKN - 1) + i;
            if (ll >= 0)
                s += g_z[(size_t)(t - (CKN - 1) + i) * ZCW + MEM + tid] * ck[i * ZCW + MEM + tid];
        }
        float lp = fminf(fmaxf(score_scale[tid] * s, -20.f), 20.f);
        float pw = expf(lp - g_slope[tid] * (float)(LLEN - 1 - l));
        spw[tid] = pw;
        g_merged[tb + tid] = pw;
    }
    __syncthreads();

    for (int c = tid; c < 768; c += 256) {
        float kv = 0.f;
#pragma unroll
        for (int i = 0; i < CKN; i++) {
            int ll = l - (CKN - 1) + i;
            if (ll >= 0)
                kv += g_z[(size_t)(t - (CKN - 1) + i) * ZCW + c] * ck[i * ZCW + c];
        }
        float phi = tanhf(kv) * g_theta[c];
        float sn, cn;
        sincosf(phi, &sn, &cn);
        float w = kv * spw[c >> 6];
        g_merged[tb + KK + c] = w * cn;
        g_merged[tb + KK + FLAT + c] = w * sn;
    }
}

// ---------------- blocked cumsum over L (3 passes, in-place) ----------------
__global__ void scan_pass1() {
    int idx = blockIdx.x * 256 + threadIdx.x;
    if (idx >= BB * NCH * CHN) return;
    int c = idx % CHN;
    int r = idx / CHN;
    int ch = r % NCH;
    int b = r / NCH;
    size_t base = ((size_t)b * LLEN + (size_t)ch * CLEN) * CHN + c;
    float s = 0.f;
#pragma unroll 4
    for (int i = 0; i < CLEN; i++) s += g_merged[base + (size_t)i * CHN];
    g_part[(b * CHN + c) * NCH + ch] = s;
}

__global__ void scan_pass2() {
    int idx = blockIdx.x * 256 + threadIdx.x;
    if (idx >= BB * CHN) return;
    int base = idx * NCH;
    float off = 0.f;
#pragma unroll
    for (int i = 0; i < NCH; i++) {
        float v = g_part[base + i];
        g_part[base + i] = off;
        off += v;
    }
}

__global__ void scan_pass3() {
    int idx = blockIdx.x * 256 + threadIdx.x;
    if (idx >= BB * NCH * CHN) return;
    int c = idx % CHN;
    int r = idx / CHN;
    int ch = r % NCH;
    int b = r / NCH;
    size_t base = ((size_t)b * LLEN + (size_t)ch * CLEN) * CHN + c;
    float run = g_part[(b * CHN + c) * NCH + ch];
    for (int i = 0; i < CLEN; i++) {
        size_t a = base + (size_t)i * CHN;
        run += g_merged[a];
        g_merged[a] = run;
    }
}

// ---------------- attention combine: cs + q -> o ----------------
__global__ __launch_bounds__(256)
void combine_q_kernel(const float* __restrict__ norm_scale) {
    const int t = blockIdx.x;
    const int tid = threadIdx.x;
    __shared__ float inv[KK];
    const int tb = t * CHN;
    if (tid < KK) {
        float d = g_merged[tb + tid];
        inv[tid] = 1.f / fmaxf(d, 1e-4f);
    }
    __syncthreads();
    for (int c = tid; c < 768; c += 256) {
        int k = c >> 6, h = c & 63, kq = k >> 1;
        float iv = inv[k];
        float sre = g_merged[tb + KK + c] * iv;
        float sim = g_merged[tb + KK + FLAT + c] * iv;
        float qre = g_q[(size_t)t * 768 + kq * 128 + 2 * h];
        float qim = g_q[(size_t)t * 768 + kq * 128 + 2 * h + 1];
        float ns = norm_scale[c];
        g_o[(size_t)t * 1536 + k * 128 + h]      = (sre * qre + sim * qim) * ns;
        g_o[(size_t)t * 1536 + k * 128 + 64 + h] = (sim * qre - sre * qim) * ns;
    }
}

// ---------------- block-diagonal spec GEMM, fused gate + highway ----------------
// grid (3, TOK/128, 12). For head z:
//   ydir[t, z*384+n] = gate(t,z) * sum_r o[t, z*128+r] * Wcat_z[r,n] + hw[z]*ydir_old
__global__ __launch_bounds__(256)
void spec_gemm_kernel(const float* __restrict__ Wre, const float* __restrict__ Wim,
                      const float* __restrict__ bg, const float* __restrict__ hw) {
    const int z = blockIdx.z;
    __shared__ float As[8][128];
    __shared__ float Bs[8][128];
    const int tid = threadIdx.x;
    const int tx = tid & 15;
    const int ty = tid >> 4;
    const int rowBase = blockIdx.y * 128;
    const int colBase = blockIdx.x * 128;   // < 384

    const int arow = tid >> 1;
    const int acol = (tid & 1) << 2;
    const int brow = tid >> 5;
    const int bcol = (tid & 31) << 2;

    float acc[8][8];
#pragma unroll
    for (int i = 0; i < 8; i++)
#pragma unroll
        for (int j = 0; j < 8; j++) acc[i][j] = 0.f;

    const float* Ap = g_o + (size_t)(rowBase + arow) * 1536 + z * 128 + acol;

    for (int k0 = 0; k0 < 128; k0 += 8) {
        float4 av = *(const float4*)(Ap + k0);
        As[acol + 0][arow] = av.x;
        As[acol + 1][arow] = av.y;
        As[acol + 2][arow] = av.z;
        As[acol + 3][arow] = av.w;
        int rr = k0 + brow;
        const float* Bp = (rr < 64) ? (Wre + (size_t)(z * 64 + rr) * DSW)
                                    : (Wim + (size_t)(z * 64 + rr - 64) * DSW);
        float4 bv = *(const float4*)(Bp + colBase + bcol);
        *(float4*)&Bs[brow][bcol] = bv;
        __syncthreads();
#pragma unroll
        for (int kk = 0; kk < 8; kk++) {
            float ar[8], br[8];
            *(float4*)&ar[0] = *(const float4*)&As[kk][ty * 8];
            *(float4*)&ar[4] = *(const float4*)&As[kk][ty * 8 + 4];
            *(float4*)&br[0] = *(const float4*)&Bs[kk][tx * 8];
            *(float4*)&br[4] = *(const float4*)&Bs[kk][tx * 8 + 4];
#pragma unroll
            for (int i = 0; i < 8; i++)
#pragma unroll
                for (int j = 0; j < 8; j++) acc[i][j] += ar[i] * br[j];
        }
        __syncthreads();
    }

    const float hwz = hw[z];
    const float bgz = bg[z];
#pragma unroll
    for (int i = 0; i < 8; i++) {
        int r = rowBase + ty * 8 + i;
        float gate = sigmoid_f(g_glin[(size_t)r * KK + z] + bgz);
        float* Drow = g_ydir + (size_t)r * 4608 + z * DSW;
#pragma unroll
        for (int j0 = 0; j0 < 8; j0 += 4) {
            int cc = colBase + tx * 8 + j0;
            float4 dv = *(float4*)(Drow + cc);
            float4 v;
            v.x = acc[i][j0 + 0] * gate + dv.x * hwz;
            v.y = acc[i][j0 + 1] * gate + dv.y * hwz;
            v.z = acc[i][j0 + 2] * gate + dv.z * hwz;
            v.w = acc[i][j0 + 3] * gate + dv.w * hwz;
            *(float4*)(Drow + cc) = v;
        }
    }
}

// ---------------- SiLU-gated combine -> ya ----------------
__global__ void combine_h_kernel() {
    int idx = blockIdx.x * 256 + threadIdx.x;
    if (idx >= TOK * 2304) return;
    int j = idx % DEXP;
    int k = (idx / DEXP) % KK;
    int t = idx / 2304;
    float yv = g_ydir[(size_t)t * 4608 + k * DSW + j];
    float yg = g_ydir[(size_t)t * 4608 + k * DSW + DEXP + j];
    g_ya[idx] = yv * yg * sigmoid_f(yg);
}

// ---------------- host ----------------
static float* sym_addr(const void* sym) {
    void* p = nullptr;
    cudaGetSymbolAddress(&p, sym);
    return (float*)p;
}

extern "C" void kernel_launch(void* const* d_in, const int* in_sizes, int n_in,
                              void* d_out, int out_size) {
    const float* x        = (const float*)d_in[0];
    const float* W_mem    = (const float*)d_in[1];
    const float* conv_k   = (const float*)d_in[2];
    const float* W_q      = (const float*)d_in[3];
    const float* th_raw   = (const float*)d_in[4];
    const float* d_slopes = (const float*)d_in[5];
    const float* sc_scale = (const float*)d_in[6];
    const float* W_re     = (const float*)d_in[7];
    const float* W_im     = (const float*)d_in[8];
    const float* n_scale  = (const float*)d_in[9];
    const float* Wg       = (const float*)d_in[10];
    const float* bg       = (const float*)d_in[11];
    const float* W_down   = (const float*)d_in[12];
    const float* W_up     = (const float*)d_in[13];
    const float* hw       = (const float*)d_in[14];
    const float* W_out    = (const float*)d_in[15];
    float* out = (float*)d_out;

    float* pz    = sym_addr(g_z);
    float* pq    = sym_addr(g_q);
    float* pglin = sym_addr(g_glin);
    float* plat  = sym_addr(g_lat);
    float* pydir = sym_addr(g_ydir);
    float* pya   = sym_addr(g_ya);

    dim3 blk(256);
    const int MB = TOK / 128;   // 128 row-blocks

    precomp_kernel<<<1, 768>>>(th_raw, d_slopes);

    // dense GEMMs
    sgemm128<<<dim3((ZCW + 127) / 128, MB), blk>>>(x, W_mem, pz, ZCW, DD, DD, ZCW, ZCW);
    sgemm128<<<dim3(6, MB), blk>>>(x, W_q, pq, 768, DD, DD, 768, 768);
    sgemm128<<<dim3(1, MB), blk>>>(x, Wg, pglin, KK, DD, DD, KK, KK);
    sgemm128<<<dim3((LAT + 127) / 128, MB), blk>>>(x, W_down, plat, LAT, DD, DD, LAT, LAT);
    sgemm128<<<dim3(36, MB), blk>>>(plat, W_up, pydir, 4608, LAT, LAT, 4608, 4608);

    // merged construction + cumsum
    build_merged_kernel<<<TOK, blk>>>(conv_k, sc_scale);
    {
        int n1 = BB * NCH * CHN;
        scan_pass1<<<(n1 + 255) / 256, blk>>>();
        int n2 = BB * CHN;
        scan_pass2<<<(n2 + 255) / 256, blk>>>();
        scan_pass3<<<(n1 + 255) / 256, blk>>>();
    }

    // attention combine + spec GEMM (fused gate+highway into ydir)
    combine_q_kernel<<<TOK, blk>>>(n_scale);
    spec_gemm_kernel<<<dim3(3, MB, KK), blk>>>(W_re, W_im, bg, hw);

    // activation + final projection
    {
        int nh = TOK * 2304;
        combine_h_kernel<<<(nh + 255) / 256, blk>>>();
    }
    sgemm128<<<dim3(6, MB), blk>>>(pya, W_out, out, DD, 2304, 2304, DD, DD);
}

// round 2
// speedup vs baseline: 1.1081x; 1.1081x over previous
#include <cuda_runtime.h>
#include <math.h>

// ---------------- problem constants ----------------
#define BB   4
#define LLEN 4096
#define DD   768
#define KK   12
#define KQ   6
#define HH   64
#define MEM  768          // K*H
#define CHN  1548         // K + 2*FLAT
#define FLAT 768
#define DSW  384
#define DEXP 192
#define LAT  192
#define CKN  4
#define TOK  (BB*LLEN)    // 16384
#define NCH  32           // scan chunks per sequence
#define CLEN 128          // elements per chunk (NCH*CLEN = L)

// packed x-projection layout: [z(780) | q(768) | glin(12) | lat(192)] = 1752
#define PW   1752
#define OFF_Z 0
#define OFF_Q 780
#define OFF_G 1548
#define OFF_D 1560

// ---------------- device scratch ----------------
__device__ float g_wcat[DD * PW];       //   5 MB : packed projection weights
__device__ float g_zq[TOK * PW];        // 114 MB : packed projections
__device__ float g_merged[TOK * CHN];   // 101 MB : merged -> in-place cumsum
__device__ float g_part[BB * CHN * NCH];
__device__ float g_o[TOK * 1536];       // 100 MB : [o_re|o_im] per k
__device__ float g_ydir[TOK * 4608];    // 302 MB : y_dir, then spec-fused result
__device__ float g_ya[TOK * 2304];      // 151 MB
__device__ float g_theta[768];
__device__ float g_slope[KK];

// ---------------- helpers ----------------
__device__ __forceinline__ float softplus_f(float x) {
    return (x > 0.f) ? x + log1pf(expf(-x)) : log1pf(expf(x));
}
__device__ __forceinline__ float sigmoid_f(float x) {
    return 1.f / (1.f + expf(-x));
}

// ---------------- precompute theta/slopes ----------------
__global__ void precomp_kernel(const float* __restrict__ theta_raw,
                               const float* __restrict__ decay_slopes) {
    int i = threadIdx.x;
    if (i < 768) g_theta[i] = softplus_f(theta_raw[i]) + 0.001f;
    if (i < KK)  g_slope[i] = softplus_f(decay_slopes[i]);
}

// ---------------- pack the four projection weights ----------------
__global__ void pack_w_kernel(const float* __restrict__ Wmem, const float* __restrict__ Wq,
                              const float* __restrict__ Wg, const float* __restrict__ Wdown) {
    int idx = blockIdx.x * 256 + threadIdx.x;
    if (idx >= DD * PW) return;
    int r = idx / PW, c = idx % PW;
    float v;
    if (c < OFF_Q)      v = Wmem[r * 780 + c];
    else if (c < OFF_G) v = Wq[r * 768 + (c - OFF_Q)];
    else if (c < OFF_D) v = Wg[r * KK + (c - OFF_G)];
    else                v = Wdown[r * LAT + (c - OFF_D)];
    g_wcat[idx] = v;
}

// ---------------- pipelined SGEMM: C[M,N] = A[M,K] * B[K,N] ----------------
// Double-buffered smem, register prefetch, 1 sync per k-tile.
// Requires: M % 128 == 0, K % 8 == 0, N % 4 == 0, all row strides % 4 == 0.
__global__ __launch_bounds__(256, 2)
void sgemm_db(const float* __restrict__ A, const float* __restrict__ B,
              float* __restrict__ C, int N, int Kd, int lda, int ldb, int ldc) {
    __shared__ float As[2][8][128];
    __shared__ float Bs[2][8][128];
    const int tid = threadIdx.x;
    const int tx = tid & 15;
    const int ty = tid >> 4;
    const int rowBase = blockIdx.y * 128;
    const int colBase = blockIdx.x * 128;

    const int arow = tid >> 1;
    const int acol = (tid & 1) << 2;
    const int brow = tid >> 5;
    const int bcol = (tid & 31) << 2;

    const float* Ap = A + (size_t)(rowBase + arow) * lda + acol;
    const int gc = colBase + bcol;
    const bool bok = (gc < N);
    const float* Bp = B + (size_t)brow * ldb + gc;

    float acc[8][8];
#pragma unroll
    for (int i = 0; i < 8; i++)
#pragma unroll
        for (int j = 0; j < 8; j++) acc[i][j] = 0.f;

    // prologue: tile 0
    {
        float4 av = *(const float4*)(Ap);
        float4 bv = bok ? *(const float4*)(Bp) : make_float4(0.f, 0.f, 0.f, 0.f);
        As[0][acol + 0][arow] = av.x;
        As[0][acol + 1][arow] = av.y;
        As[0][acol + 2][arow] = av.z;
        As[0][acol + 3][arow] = av.w;
        *(float4*)&Bs[0][brow][bcol] = bv;
    }
    __syncthreads();

    const int nIter = Kd >> 3;
    for (int it = 0; it < nIter; it++) {
        const int buf = it & 1;
        float4 an, bn;
        const bool more = (it + 1 < nIter);
        if (more) {
            an = *(const float4*)(Ap + ((it + 1) << 3));
            bn = bok ? *(const float4*)(Bp + (size_t)((it + 1) << 3) * ldb)
                     : make_float4(0.f, 0.f, 0.f, 0.f);
        }
#pragma unroll
        for (int kk = 0; kk < 8; kk++) {
            float ar[8], br[8];
            *(float4*)&ar[0] = *(const float4*)&As[buf][kk][ty * 8];
            *(float4*)&ar[4] = *(const float4*)&As[buf][kk][ty * 8 + 4];
            *(float4*)&br[0] = *(const float4*)&Bs[buf][kk][tx * 8];
            *(float4*)&br[4] = *(const float4*)&Bs[buf][kk][tx * 8 + 4];
#pragma unroll
            for (int i = 0; i < 8; i++)
#pragma unroll
                for (int j = 0; j < 8; j++) acc[i][j] += ar[i] * br[j];
        }
        if (more) {
            const int nb = buf ^ 1;
            As[nb][acol + 0][arow] = an.x;
            As[nb][acol + 1][arow] = an.y;
            As[nb][acol + 2][arow] = an.z;
            As[nb][acol + 3][arow] = an.w;
            *(float4*)&Bs[nb][brow][bcol] = bn;
            __syncthreads();
        }
    }

#pragma unroll
    for (int i = 0; i < 8; i++) {
        int r = rowBase + ty * 8 + i;
        float* Crow = C + (size_t)r * ldc;
#pragma unroll
        for (int j0 = 0; j0 < 8; j0 += 4) {
            int cc = colBase + tx * 8 + j0;
            if (cc < N) {
                float4 v = make_float4(acc[i][j0], acc[i][j0 + 1],
                                       acc[i][j0 + 2], acc[i][j0 + 3]);
                *(float4*)(Crow + cc) = v;
            }
        }
    }
}

// ---------------- conv + merged construction ----------------
// merged layout per token: [0,12) p_w ; [12,780) re_k ; [780,1548) im_k
__global__ __launch_bounds__(256)
void build_merged_kernel(const float* __restrict__ ck,
                         const float* __restrict__ score_scale) {
    const int t = blockIdx.x;
    const int l = t & (LLEN - 1);
    const int tid = threadIdx.x;
    __shared__ float spw[KK];
    const int tb = t * CHN;

    if (tid < KK) {
        float s = 0.f;
#pragma unroll
        for (int i = 0; i < CKN; i++) {
            int ll = l - (CKN - 1) + i;
            if (ll >= 0)
                s += g_zq[(size_t)(t - (CKN - 1) + i) * PW + MEM + tid] * ck[i * 780 + MEM + tid];
        }
        float lp = fminf(fmaxf(score_scale[tid] * s, -20.f), 20.f);
        float pw = expf(lp - g_slope[tid] * (float)(LLEN - 1 - l));
        spw[tid] = pw;
        g_merged[tb + tid] = pw;
    }
    __syncthreads();

    for (int c = tid; c < 768; c += 256) {
        float kv = 0.f;
#pragma unroll
        for (int i = 0; i < CKN; i++) {
            int ll = l - (CKN - 1) + i;
            if (ll >= 0)
                kv += g_zq[(size_t)(t - (CKN - 1) + i) * PW + c] * ck[i * 780 + c];
        }
        float phi = tanhf(kv) * g_theta[c];
        float sn, cn;
        sincosf(phi, &sn, &cn);
        float w = kv * spw[c >> 6];
        g_merged[tb + KK + c] = w * cn;
        g_merged[tb + KK + FLAT + c] = w * sn;
    }
}

// ---------------- blocked cumsum over L (3 passes, in-place) ----------------
__global__ void scan_pass1() {
    int idx = blockIdx.x * 256 + threadIdx.x;
    if (idx >= BB * NCH * CHN) return;
    int c = idx % CHN;
    int r = idx / CHN;
    int ch = r % NCH;
    int b = r / NCH;
    size_t base = ((size_t)b * LLEN + (size_t)ch * CLEN) * CHN + c;
    float s = 0.f;
#pragma unroll 4
    for (int i = 0; i < CLEN; i++) s += g_merged[base + (size_t)i * CHN];
    g_part[(b * CHN + c) * NCH + ch] = s;
}

__global__ void scan_pass2() {
    int idx = blockIdx.x * 256 + threadIdx.x;
    if (idx >= BB * CHN) return;
    int base = idx * NCH;
    float off = 0.f;
#pragma unroll
    for (int i = 0; i < NCH; i++) {
        float v = g_part[base + i];
        g_part[base + i] = off;
        off += v;
    }
}

__global__ void scan_pass3() {
    int idx = blockIdx.x * 256 + threadIdx.x;
    if (idx >= BB * NCH * CHN) return;
    int c = idx % CHN;
    int r = idx / CHN;
    int ch = r % NCH;
    int b = r / NCH;
    size_t base = ((size_t)b * LLEN + (size_t)ch * CLEN) * CHN + c;
    float run = g_part[(b * CHN + c) * NCH + ch];
    for (int i = 0; i < CLEN; i++) {
        size_t a = base + (size_t)i * CHN;
        run += g_merged[a];
        g_merged[a] = run;
    }
}

// ---------------- attention combine: cs + q -> o ----------------
__global__ __launch_bounds__(256)
void combine_q_kernel(const float* __restrict__ norm_scale) {
    const int t = blockIdx.x;
    const int tid = threadIdx.x;
    __shared__ float inv[KK];
    const int tb = t * CHN;
    if (tid < KK) {
        float d = g_merged[tb + tid];
        inv[tid] = 1.f / fmaxf(d, 1e-4f);
    }
    __syncthreads();
    for (int c = tid; c < 768; c += 256) {
        int k = c >> 6, h = c & 63, kq = k >> 1;
        float iv = inv[k];
        float sre = g_merged[tb + KK + c] * iv;
        float sim = g_merged[tb + KK + FLAT + c] * iv;
        float qre = g_zq[(size_t)t * PW + OFF_Q + kq * 128 + 2 * h];
        float qim = g_zq[(size_t)t * PW + OFF_Q + kq * 128 + 2 * h + 1];
        float ns = norm_scale[c];
        g_o[(size_t)t * 1536 + k * 128 + h]      = (sre * qre + sim * qim) * ns;
        g_o[(size_t)t * 1536 + k * 128 + 64 + h] = (sim * qre - sre * qim) * ns;
    }
}

// ---------------- block-diagonal spec GEMM, fused gate + highway ----------------
// grid (3, TOK/128, 12). For head z:
//   ydir[t, z*384+n] = gate(t,z) * sum_r o[t, z*128+r] * Wcat_z[r,n] + hw[z]*ydir_old
__global__ __launch_bounds__(256, 2)
void spec_gemm_kernel(const float* __restrict__ Wre, const float* __restrict__ Wim,
                      const float* __restrict__ bg, const float* __restrict__ hw) {
    const int z = blockIdx.z;
    __shared__ float As[2][8][128];
    __shared__ float Bs[2][8][128];
    const int tid = threadIdx.x;
    const int tx = tid & 15;
    const int ty = tid >> 4;
    const int rowBase = blockIdx.y * 128;
    const int colBase = blockIdx.x * 128;   // < 384, exact

    const int arow = tid >> 1;
    const int acol = (tid & 1) << 2;
    const int brow = tid >> 5;
    const int bcol = (tid & 31) << 2;

    float acc[8][8];
#pragma unroll
    for (int i = 0; i < 8; i++)
#pragma unroll
        for (int j = 0; j < 8; j++) acc[i][j] = 0.f;

    const float* Ap = g_o + (size_t)(rowBase + arow) * 1536 + z * 128 + acol;
    const float* WreZ = Wre + (size_t)z * 64 * DSW + colBase + bcol;
    const float* WimZ = Wim + (size_t)z * 64 * DSW + colBase + bcol;

    // prologue: tile 0 (rows 0..7, all in Wre)
    {
        float4 av = *(const float4*)(Ap);
        float4 bv = *(const float4*)(WreZ + (size_t)brow * DSW);
        As[0][acol + 0][arow] = av.x;
        As[0][acol + 1][arow] = av.y;
        As[0][acol + 2][arow] = av.z;
        As[0][acol + 3][arow] = av.w;
        *(float4*)&Bs[0][brow][bcol] = bv;
    }
    __syncthreads();

    const int nIter = 16;  // K = 128
    for (int it = 0; it < nIter; it++) {
        const int buf = it & 1;
        float4 an, bn;
        const bool more = (it + 1 < nIter);
        if (more) {
            int k1 = (it + 1) << 3;
            an = *(const float4*)(Ap + k1);
            int rr = k1 + brow;
            const float* Bp = (rr < 64) ? (WreZ + (size_t)rr * DSW)
                                        : (WimZ + (size_t)(rr - 64) * DSW);
            bn = *(const float4*)(Bp);
        }
#pragma unroll
        for (int kk = 0; kk < 8; kk++) {
            float ar[8], br[8];
            *(float4*)&ar[0] = *(const float4*)&As[buf][kk][ty * 8];
            *(float4*)&ar[4] = *(const float4*)&As[buf][kk][ty * 8 + 4];
            *(float4*)&br[0] = *(const float4*)&Bs[buf][kk][tx * 8];
            *(float4*)&br[4] = *(const float4*)&Bs[buf][kk][tx * 8 + 4];
#pragma unroll
            for (int i = 0; i < 8; i++)
#pragma unroll
                for (int j = 0; j < 8; j++) acc[i][j] += ar[i] * br[j];
        }
        if (more) {
            const int nb = buf ^ 1;
            As[nb][acol + 0][arow] = an.x;
            As[nb][acol + 1][arow] = an.y;
            As[nb][acol + 2][arow] = an.z;
            As[nb][acol + 3][arow] = an.w;
            *(float4*)&Bs[nb][brow][bcol] = bn;
            __syncthreads();
        }
    }

    const float hwz = hw[z];
    const float bgz = bg[z];
#pragma unroll
    for (int i = 0; i < 8; i++) {
        int r = rowBase + ty * 8 + i;
        float gate = sigmoid_f(g_zq[(size_t)r * PW + OFF_G + z] + bgz);
        float* Drow = g_ydir + (size_t)r * 4608 + z * DSW;
#pragma unroll
        for (int j0 = 0; j0 < 8; j0 += 4) {
            int cc = colBase + tx * 8 + j0;
            float4 dv = *(float4*)(Drow + cc);
            float4 v;
            v.x = acc[i][j0 + 0] * gate + dv.x * hwz;
            v.y = acc[i][j0 + 1] * gate + dv.y * hwz;
            v.z = acc[i][j0 + 2] * gate + dv.z * hwz;
            v.w = acc[i][j0 + 3] * gate + dv.w * hwz;
            *(float4*)(Drow + cc) = v;
        }
    }
}

// ---------------- SiLU-gated combine -> ya (vectorized) ----------------
__global__ void combine_h_kernel() {
    int idx4 = blockIdx.x * 256 + threadIdx.x;
    if (idx4 >= TOK * 2304 / 4) return;
    int idx = idx4 * 4;
    int j = idx % DEXP;
    int k = (idx / DEXP) % KK;
    int t = idx / 2304;
    const float* base = g_ydir + (size_t)t * 4608 + k * DSW + j;
    float4 yv = *(const float4*)(base);
    float4 yg = *(const float4*)(base + DEXP);
    float4 r;
    r.x = yv.x * yg.x * sigmoid_f(yg.x);
    r.y = yv.y * yg.y * sigmoid_f(yg.y);
    r.z = yv.z * yg.z * sigmoid_f(yg.z);
    r.w = yv.w * yg.w * sigmoid_f(yg.w);
    *(float4*)(g_ya + idx) = r;
}

// ---------------- host ----------------
static float* sym_addr(const void* sym) {
    void* p = nullptr;
    cudaGetSymbolAddress(&p, sym);
    return (float*)p;
}

extern "C" void kernel_launch(void* const* d_in, const int* in_sizes, int n_in,
                              void* d_out, int out_size) {
    const float* x        = (const float*)d_in[0];
    const float* W_mem    = (const float*)d_in[1];
    const float* conv_k   = (const float*)d_in[2];
    const float* W_q      = (const float*)d_in[3];
    const float* th_raw   = (const float*)d_in[4];
    const float* d_slopes = (const float*)d_in[5];
    const float* sc_scale = (const float*)d_in[6];
    const float* W_re     = (const float*)d_in[7];
    const float* W_im     = (const float*)d_in[8];
    const float* n_scale  = (const float*)d_in[9];
    const float* Wg       = (const float*)d_in[10];
    const float* bg       = (const float*)d_in[11];
    const float* W_down   = (const float*)d_in[12];
    const float* W_up     = (const float*)d_in[13];
    const float* hw       = (const float*)d_in[14];
    const float* W_out    = (const float*)d_in[15];
    float* out = (float*)d_out;

    float* pwcat = sym_addr(g_wcat);
    float* pzq   = sym_addr(g_zq);
    float* pydir = sym_addr(g_ydir);
    float* pya   = sym_addr(g_ya);

    dim3 blk(256);
    const int MB = TOK / 128;   // 128 row-blocks

    precomp_kernel<<<1, 768>>>(th_raw, d_slopes);
    pack_w_kernel<<<(DD * PW + 255) / 256, blk>>>(W_mem, W_q, Wg, W_down);

    // fused projection GEMM: x[16384,768] @ Wcat[768,1752] -> zq
    sgemm_db<<<dim3((PW + 127) / 128, MB), blk>>>(x, pwcat, pzq, PW, DD, DD, PW, PW);

    // W_up GEMM: lat slice of zq -> ydir
    sgemm_db<<<dim3(36, MB), blk>>>(pzq + OFF_D, W_up, pydir, 4608, LAT, PW, 4608, 4608);

    // merged construction + cumsum
    build_merged_kernel<<<TOK, blk>>>(conv_k, sc_scale);
    {
        int n1 = BB * NCH * CHN;
        scan_pass1<<<(n1 + 255) / 256, blk>>>();
        int n2 = BB * CHN;
        scan_pass2<<<(n2 + 255) / 256, blk>>>();
        scan_pass3<<<(n1 + 255) / 256, blk>>>();
    }

    // attention combine + spec GEMM (fused gate+highway into ydir)
    combine_q_kernel<<<TOK, blk>>>(n_scale);
    spec_gemm_kernel<<<dim3(3, MB, KK), blk>>>(W_re, W_im, bg, hw);

    // activation + final projection
    {
        int nh = TOK * 2304 / 4;
        combine_h_kernel<<<(nh + 255) / 256, blk>>>();
    }
    sgemm_db<<<dim3(6, MB), blk>>>(pya, W_out, out, DD, 2304, 2304, DD, DD);
}

// round 4
// speedup vs baseline: 1.2551x; 1.1327x over previous
#include <cuda_runtime.h>
#include <math.h>

// ---------------- problem constants ----------------
#define BB   4
#define LLEN 4096
#define DD   768
#define KK   12
#define KQ   6
#define HH   64
#define MEM  768          // K*H
#define CHN  1548         // K + 2*FLAT
#define FLAT 768
#define DSW  384
#define DEXP 192
#define LAT  192
#define CKN  4
#define TOK  (BB*LLEN)    // 16384
#define NCH  32           // scan chunks per sequence
#define CLEN 128          // elements per chunk (NCH*CLEN = L)

// packed x-projection layout: [z(780) | q(768) | glin(12) | lat(192)] = 1752
#define PW   1752
#define OFF_Q 780
#define OFF_G 1548
#define OFF_D 1560

// ---------------- device scratch ----------------
__device__ float g_wcat[DD * PW];       //   5 MB : packed projection weights
__device__ float g_zq[TOK * PW];        // 114 MB : packed projections
__device__ float g_merged[TOK * CHN];   // 101 MB : merged -> in-place cumsum
__device__ float g_part[BB * CHN * NCH];
__device__ float g_o[TOK * 1536];       // 100 MB : [o_re|o_im] per k
__device__ float g_ydir[TOK * 4608];    // 302 MB : y_dir, then spec-fused result
__device__ float g_ya[TOK * 2304];      // 151 MB
__device__ float g_theta[768];
__device__ float g_slope[KK];

// ---------------- helpers ----------------
__device__ __forceinline__ float softplus_f(float x) {
    return (x > 0.f) ? x + log1pf(expf(-x)) : log1pf(expf(x));
}
__device__ __forceinline__ float sigmoid_f(float x) {
    return 1.f / (1.f + expf(-x));
}

// ---------------- precompute theta/slopes ----------------
__global__ void precomp_kernel(const float* __restrict__ theta_raw,
                               const float* __restrict__ decay_slopes) {
    int i = threadIdx.x;
    if (i < 768) g_theta[i] = softplus_f(theta_raw[i]) + 0.001f;
    if (i < KK)  g_slope[i] = softplus_f(decay_slopes[i]);
}

// ---------------- pack the four projection weights ----------------
__global__ void pack_w_kernel(const float* __restrict__ Wmem, const float* __restrict__ Wq,
                              const float* __restrict__ Wg, const float* __restrict__ Wdown) {
    int idx = blockIdx.x * 256 + threadIdx.x;
    if (idx >= DD * PW) return;
    int r = idx / PW, c = idx % PW;
    float v;
    if (c < OFF_Q)      v = Wmem[r * 780 + c];
    else if (c < OFF_G) v = Wq[r * 768 + (c - OFF_Q)];
    else if (c < OFF_D) v = Wg[r * KK + (c - OFF_G)];
    else                v = Wdown[r * LAT + (c - OFF_D)];
    g_wcat[idx] = v;
}

// ---------------- pipelined SGEMM, conflict-free split fragments ----------------
// C[M,N] = A[M,K] * B[K,N]. Thread (tx,ty) owns rows {ty*4..+3, 64+ty*4..+3},
// cols {tx*4..+3, 64+tx*4..+3}. LDS phases: A-frag broadcast, B-frag contiguous.
__global__ __launch_bounds__(256, 2)
void sgemm_db(const float* __restrict__ A, const float* __restrict__ B,
              float* __restrict__ C, int N, int Kd, int lda, int ldb, int ldc) {
    __shared__ float As[2][8][128];
    __shared__ float Bs[2][8][128];
    const int tid = threadIdx.x;
    const int tx = tid & 15;
    const int ty = tid >> 4;
    const int rowBase = blockIdx.y * 128;
    const int colBase = blockIdx.x * 128;

    const int arow = tid >> 1;
    const int acol = (tid & 1) << 2;
    const int brow = tid >> 5;
    const int bcol = (tid & 31) << 2;

    const float* Ap = A + (size_t)(rowBase + arow) * lda + acol;
    const int gc = colBase + bcol;
    const bool bok = (gc < N);
    const float* Bp = B + (size_t)brow * ldb + gc;

    float acc[8][8];
#pragma unroll
    for (int i = 0; i < 8; i++)
#pragma unroll
        for (int j = 0; j < 8; j++) acc[i][j] = 0.f;

    // prologue: tile 0
    {
        float4 av = *(const float4*)(Ap);
        float4 bv = bok ? *(const float4*)(Bp) : make_float4(0.f, 0.f, 0.f, 0.f);
        As[0][acol + 0][arow] = av.x;
        As[0][acol + 1][arow] = av.y;
        As[0][acol + 2][arow] = av.z;
        As[0][acol + 3][arow] = av.w;
        *(float4*)&Bs[0][brow][bcol] = bv;
    }
    __syncthreads();

    const int nIter = Kd >> 3;
    for (int it = 0; it < nIter; it++) {
        const int buf = it & 1;
        float4 an, bn;
        const bool more = (it + 1 < nIter);
        if (more) {
            an = *(const float4*)(Ap + ((it + 1) << 3));
            bn = bok ? *(const float4*)(Bp + (size_t)((it + 1) << 3) * ldb)
                     : make_float4(0.f, 0.f, 0.f, 0.f);
        }
#pragma unroll
        for (int kk = 0; kk < 8; kk++) {
            float ar[8], br[8];
            *(float4*)&ar[0] = *(const float4*)&As[buf][kk][ty * 4];
            *(float4*)&ar[4] = *(const float4*)&As[buf][kk][64 + ty * 4];
            *(float4*)&br[0] = *(const float4*)&Bs[buf][kk][tx * 4];
            *(float4*)&br[4] = *(const float4*)&Bs[buf][kk][64 + tx * 4];
#pragma unroll
            for (int i = 0; i < 8; i++)
#pragma unroll
                for (int j = 0; j < 8; j++) acc[i][j] += ar[i] * br[j];
        }
        if (more) {
            const int nb = buf ^ 1;
            As[nb][acol + 0][arow] = an.x;
            As[nb][acol + 1][arow] = an.y;
            As[nb][acol + 2][arow] = an.z;
            As[nb][acol + 3][arow] = an.w;
            *(float4*)&Bs[nb][brow][bcol] = bn;
            __syncthreads();
        }
    }

#pragma unroll
    for (int h = 0; h < 2; h++)
#pragma unroll
        for (int i = 0; i < 4; i++) {
            int r = rowBase + h * 64 + ty * 4 + i;
            float* Crow = C + (size_t)r * ldc;
#pragma unroll
            for (int jh = 0; jh < 2; jh++) {
                int cc = colBase + jh * 64 + tx * 4;
                if (cc < N) {
                    float4 v = make_float4(acc[h * 4 + i][jh * 4 + 0], acc[h * 4 + i][jh * 4 + 1],
                                           acc[h * 4 + i][jh * 4 + 2], acc[h * 4 + i][jh * 4 + 3]);
                    *(float4*)(Crow + cc) = v;
                }
            }
        }
}

// ---------------- conv + merged construction ----------------
// merged layout per token: [0,12) p_w ; [12,780) re_k ; [780,1548) im_k
__global__ __launch_bounds__(256)
void build_merged_kernel(const float* __restrict__ ck,
                         const float* __restrict__ score_scale) {
    const int t = blockIdx.x;
    const int l = t & (LLEN - 1);
    const int tid = threadIdx.x;
    __shared__ float spw[KK];
    const int tb = t * CHN;

    if (tid < KK) {
        float s = 0.f;
#pragma unroll
        for (int i = 0; i < CKN; i++) {
            int ll = l - (CKN - 1) + i;
            if (ll >= 0)
                s += g_zq[(size_t)(t - (CKN - 1) + i) * PW + MEM + tid] * ck[i * 780 + MEM + tid];
        }
        float lp = fminf(fmaxf(score_scale[tid] * s, -20.f), 20.f);
        float pw = expf(lp - g_slope[tid] * (float)(LLEN - 1 - l));
        spw[tid] = pw;
        g_merged[tb + tid] = pw;
    }
    __syncthreads();

    for (int c = tid; c < 768; c += 256) {
        float kv = 0.f;
#pragma unroll
        for (int i = 0; i < CKN; i++) {
            int ll = l - (CKN - 1) + i;
            if (ll >= 0)
                kv += g_zq[(size_t)(t - (CKN - 1) + i) * PW + c] * ck[i * 780 + c];
        }
        float phi = tanhf(kv) * g_theta[c];
        float sn, cn;
        sincosf(phi, &sn, &cn);
        float w = kv * spw[c >> 6];
        g_merged[tb + KK + c] = w * cn;
        g_merged[tb + KK + FLAT + c] = w * sn;
    }
}

// ---------------- blocked cumsum over L (3 passes, in-place) ----------------
__global__ void scan_pass1() {
    int idx = blockIdx.x * 256 + threadIdx.x;
    if (idx >= BB * NCH * CHN) return;
    int c = idx % CHN;
    int r = idx / CHN;
    int ch = r % NCH;
    int b = r / NCH;
    size_t base = ((size_t)b * LLEN + (size_t)ch * CLEN) * CHN + c;
    float s = 0.f;
#pragma unroll 4
    for (int i = 0; i < CLEN; i++) s += g_merged[base + (size_t)i * CHN];
    g_part[(b * CHN + c) * NCH + ch] = s;
}

__global__ void scan_pass2() {
    int idx = blockIdx.x * 256 + threadIdx.x;
    if (idx >= BB * CHN) return;
    int base = idx * NCH;
    float off = 0.f;
#pragma unroll
    for (int i = 0; i < NCH; i++) {
        float v = g_part[base + i];
        g_part[base + i] = off;
        off += v;
    }
}

__global__ void scan_pass3() {
    int idx = blockIdx.x * 256 + threadIdx.x;
    if (idx >= BB * NCH * CHN) return;
    int c = idx % CHN;
    int r = idx / CHN;
    int ch = r % NCH;
    int b = r / NCH;
    size_t base = ((size_t)b * LLEN + (size_t)ch * CLEN) * CHN + c;
    float run = g_part[(b * CHN + c) * NCH + ch];
    for (int i = 0; i < CLEN; i++) {
        size_t a = base + (size_t)i * CHN;
        run += g_merged[a];
        g_merged[a] = run;
    }
}

// ---------------- attention combine: cs + q -> o ----------------
__global__ __launch_bounds__(256)
void combine_q_kernel(const float* __restrict__ norm_scale) {
    const int t = blockIdx.x;
    const int tid = threadIdx.x;
    __shared__ float inv[KK];
    const int tb = t * CHN;
    if (tid < KK) {
        float d = g_merged[tb + tid];
        inv[tid] = 1.f / fmaxf(d, 1e-4f);
    }
    __syncthreads();
    for (int c = tid; c < 768; c += 256) {
        int k = c >> 6, h = c & 63, kq = k >> 1;
        float iv = inv[k];
        float sre = g_merged[tb + KK + c] * iv;
        float sim = g_merged[tb + KK + FLAT + c] * iv;
        float qre = g_zq[(size_t)t * PW + OFF_Q + kq * 128 + 2 * h];
        float qim = g_zq[(size_t)t * PW + OFF_Q + kq * 128 + 2 * h + 1];
        float ns = norm_scale[c];
        g_o[(size_t)t * 1536 + k * 128 + h]      = (sre * qre + sim * qim) * ns;
        g_o[(size_t)t * 1536 + k * 128 + 64 + h] = (sim * qre - sre * qim) * ns;
    }
}

// ---------------- block-diagonal spec GEMM, fused gate + highway ----------------
// grid (3, TOK/128, 12). Split-fragment layout like sgemm_db.
__global__ __launch_bounds__(256, 2)
void spec_gemm_kernel(const float* __restrict__ Wre, const float* __restrict__ Wim,
                      const float* __restrict__ bg, const float* __restrict__ hw) {
    const int z = blockIdx.z;
    __shared__ float As[2][8][128];
    __shared__ float Bs[2][8][128];
    const int tid = threadIdx.x;
    const int tx = tid & 15;
    const int ty = tid >> 4;
    const int rowBase = blockIdx.y * 128;
    const int colBase = blockIdx.x * 128;   // < 384, exact

    const int arow = tid >> 1;
    const int acol = (tid & 1) << 2;
    const int brow = tid >> 5;
    const int bcol = (tid & 31) << 2;

    float acc[8][8];
#pragma unroll
    for (int i = 0; i < 8; i++)
#pragma unroll
        for (int j = 0; j < 8; j++) acc[i][j] = 0.f;

    const float* Ap = g_o + (size_t)(rowBase + arow) * 1536 + z * 128 + acol;
    const float* WreZ = Wre + (size_t)z * 64 * DSW + colBase + bcol;
    const float* WimZ = Wim + (size_t)z * 64 * DSW + colBase + bcol;

    // prologue: tile 0 (rows 0..7, all in Wre)
    {
        float4 av = *(const float4*)(Ap);
        float4 bv = *(const float4*)(WreZ + (size_t)brow * DSW);
        As[0][acol + 0][arow] = av.x;
        As[0][acol + 1][arow] = av.y;
        As[0][acol + 2][arow] = av.z;
        As[0][acol + 3][arow] = av.w;
        *(float4*)&Bs[0][brow][bcol] = bv;
    }
    __syncthreads();

    const int nIter = 16;  // K = 128
    for (int it = 0; it < nIter; it++) {
        const int buf = it & 1;
        float4 an, bn;
        const bool more = (it + 1 < nIter);
        if (more) {
            int k1 = (it + 1) << 3;
            an = *(const float4*)(Ap + k1);
            int rr = k1 + brow;
            const float* Bp = (rr < 64) ? (WreZ + (size_t)rr * DSW)
                                        : (WimZ + (size_t)(rr - 64) * DSW);
            bn = *(const float4*)(Bp);
        }
#pragma unroll
        for (int kk = 0; kk < 8; kk++) {
            float ar[8], br[8];
            *(float4*)&ar[0] = *(const float4*)&As[buf][kk][ty * 4];
            *(float4*)&ar[4] = *(const float4*)&As[buf][kk][64 + ty * 4];
            *(float4*)&br[0] = *(const float4*)&Bs[buf][kk][tx * 4];
            *(float4*)&br[4] = *(const float4*)&Bs[buf][kk][64 + tx * 4];
#pragma unroll
            for (int i = 0; i < 8; i++)
#pragma unroll
                for (int j = 0; j < 8; j++) acc[i][j] += ar[i] * br[j];
        }
        if (more) {
            const int nb = buf ^ 1;
            As[nb][acol + 0][arow] = an.x;
            As[nb][acol + 1][arow] = an.y;
            As[nb][acol + 2][arow] = an.z;
            As[nb][acol + 3][arow] = an.w;
            *(float4*)&Bs[nb][brow][bcol] = bn;
            __syncthreads();
        }
    }

    const float hwz = hw[z];
    const float bgz = bg[z];
#pragma unroll
    for (int h = 0; h < 2; h++)
#pragma unroll
        for (int i = 0; i < 4; i++) {
            int r = rowBase + h * 64 + ty * 4 + i;
            float gate = sigmoid_f(g_zq[(size_t)r * PW + OFF_G + z] + bgz);
            float* Drow = g_ydir + (size_t)r * 4608 + z * DSW;
#pragma unroll
            for (int jh = 0; jh < 2; jh++) {
                int cc = colBase + jh * 64 + tx * 4;
                float4 dv = *(float4*)(Drow + cc);
                float4 v;
                v.x = acc[h * 4 + i][jh * 4 + 0] * gate + dv.x * hwz;
                v.y = acc[h * 4 + i][jh * 4 + 1] * gate + dv.y * hwz;
                v.z = acc[h * 4 + i][jh * 4 + 2] * gate + dv.z * hwz;
                v.w = acc[h * 4 + i][jh * 4 + 3] * gate + dv.w * hwz;
                *(float4*)(Drow + cc) = v;
            }
        }
}

// ---------------- SiLU-gated combine -> ya (vectorized) ----------------
__global__ void combine_h_kernel() {
    int idx4 = blockIdx.x * 256 + threadIdx.x;
    if (idx4 >= TOK * 2304 / 4) return;
    int idx = idx4 * 4;
    int j = idx % DEXP;
    int k = (idx / DEXP) % KK;
    int t = idx / 2304;
    const float* base = g_ydir + (size_t)t * 4608 + k * DSW + j;
    float4 yv = *(const float4*)(base);
    float4 yg = *(const float4*)(base + DEXP);
    float4 r;
    r.x = yv.x * yg.x * sigmoid_f(yg.x);
    r.y = yv.y * yg.y * sigmoid_f(yg.y);
    r.z = yv.z * yg.z * sigmoid_f(yg.z);
    r.w = yv.w * yg.w * sigmoid_f(yg.w);
    *(float4*)(g_ya + idx) = r;
}

// ---------------- host ----------------
static float* sym_addr(const void* sym) {
    void* p = nullptr;
    cudaGetSymbolAddress(&p, sym);
    return (float*)p;
}

extern "C" void kernel_launch(void* const* d_in, const int* in_sizes, int n_in,
                              void* d_out, int out_size) {
    const float* x        = (const float*)d_in[0];
    const float* W_mem    = (const float*)d_in[1];
    const float* conv_k   = (const float*)d_in[2];
    const float* W_q      = (const float*)d_in[3];
    const float* th_raw   = (const float*)d_in[4];
    const float* d_slopes = (const float*)d_in[5];
    const float* sc_scale = (const float*)d_in[6];
    const float* W_re     = (const float*)d_in[7];
    const float* W_im     = (const float*)d_in[8];
    const float* n_scale  = (const float*)d_in[9];
    const float* Wg       = (const float*)d_in[10];
    const float* bg       = (const float*)d_in[11];
    const float* W_down   = (const float*)d_in[12];
    const float* W_up     = (const float*)d_in[13];
    const float* hw       = (const float*)d_in[14];
    const float* W_out    = (const float*)d_in[15];
    float* out = (float*)d_out;

    float* pwcat = sym_addr(g_wcat);
    float* pzq   = sym_addr(g_zq);
    float* pydir = sym_addr(g_ydir);
    float* pya   = sym_addr(g_ya);

    dim3 blk(256);
    const int MB = TOK / 128;   // 128 row-blocks

    precomp_kernel<<<1, 768>>>(th_raw, d_slopes);
    pack_w_kernel<<<(DD * PW + 255) / 256, blk>>>(W_mem, W_q, Wg, W_down);

    // fused projection GEMM: x[16384,768] @ Wcat[768,1752] -> zq
    sgemm_db<<<dim3((PW + 127) / 128, MB), blk>>>(x, pwcat, pzq, PW, DD, DD, PW, PW);

    // W_up GEMM: lat slice of zq -> ydir
    sgemm_db<<<dim3(36, MB), blk>>>(pzq + OFF_D, W_up, pydir, 4608, LAT, PW, 4608, 4608);

    // merged construction + cumsum
    build_merged_kernel<<<TOK, blk>>>(conv_k, sc_scale);
    {
        int n1 = BB * NCH * CHN;
        scan_pass1<<<(n1 + 255) / 256, blk>>>();
        int n2 = BB * CHN;
        scan_pass2<<<(n2 + 255) / 256, blk>>>();
        scan_pass3<<<(n1 + 255) / 256, blk>>>();
    }

    // attention combine + spec GEMM (fused gate+highway into ydir)
    combine_q_kernel<<<TOK, blk>>>(n_scale);
    spec_gemm_kernel<<<dim3(3, MB, KK), blk>>>(W_re, W_im, bg, hw);

    // activation + final projection
    {
        int nh = TOK * 2304 / 4;
        combine_h_kernel<<<(nh + 255) / 256, blk>>>();
    }
    sgemm_db<<<dim3(6, MB), blk>>>(pya, W_out, out, DD, 2304, 2304, DD, DD);
}

// round 5
// speedup vs baseline: 2.5654x; 2.0439x over previous
#include <cuda_runtime.h>
#include <math.h>
#include <stdint.h>

// ---------------- problem constants ----------------
#define BB   4
#define LLEN 4096
#define DD   768
#define KK   12
#define KQ   6
#define HH   64
#define MEM  768          // K*H
#define CHN  1548         // K + 2*FLAT
#define FLAT 768
#define DSW  384
#define DEXP 192
#define LAT  192
#define CKN  4
#define TOK  (BB*LLEN)    // 16384
#define NCH  32           // scan chunks per sequence
#define CLEN 128          // elements per chunk (NCH*CLEN = L)

// packed x-projection layout: [z(780) | q(768) | glin(12) | lat(192)] = 1752
#define PW   1752
#define OFF_Q 780
#define OFF_G 1548
#define OFF_D 1560

// ---------------- device scratch ----------------
__device__ float g_wcatT[PW * DD];       //   5 MB : packed proj weights, [N,K] K-major
__device__ float g_wupT[4608 * LAT];     //   3.5MB
__device__ float g_woutT[DD * 2304];     //   7 MB
__device__ float g_zq[TOK * PW];         // 114 MB
__device__ float g_merged[TOK * CHN];    // 101 MB
__device__ float g_part[BB * CHN * NCH];
__device__ float g_o[TOK * 1536];        // 100 MB
__device__ float g_ydir[TOK * 4608];     // 302 MB
__device__ float g_ya[TOK * 2304];       // 151 MB
__device__ float g_theta[768];
__device__ float g_slope[KK];

// ---------------- helpers ----------------
__device__ __forceinline__ float softplus_f(float x) {
    return (x > 0.f) ? x + log1pf(expf(-x)) : log1pf(expf(x));
}
__device__ __forceinline__ float sigmoid_f(float x) {
    return 1.f / (1.f + expf(-x));
}
__device__ __forceinline__ uint32_t smem_u32(const void* p) {
    uint32_t a;
    asm("{ .reg .u64 t; cvta.to.shared.u64 t, %1; cvt.u32.u64 %0, t; }" : "=r"(a) : "l"(p));
    return a;
}
__device__ __forceinline__ uint32_t cvt_tf32(float f) {
    uint32_t u;
    asm("cvt.rna.tf32.f32 %0, %1;" : "=r"(u) : "f"(f));
    return u;
}
__device__ __forceinline__ void ldsm4(uint32_t* r, uint32_t addr) {
    asm volatile("ldmatrix.sync.aligned.m8n8.x4.shared.b16 {%0,%1,%2,%3}, [%4];"
        : "=r"(r[0]), "=r"(r[1]), "=r"(r[2]), "=r"(r[3]) : "r"(addr));
}
__device__ __forceinline__ void mma_tf32(float* d, const uint32_t* a, uint32_t b0, uint32_t b1) {
    asm volatile("mma.sync.aligned.m16n8k8.row.col.f32.tf32.tf32.f32 "
        "{%0,%1,%2,%3}, {%4,%5,%6,%7}, {%8,%9}, {%0,%1,%2,%3};"
        : "+f"(d[0]), "+f"(d[1]), "+f"(d[2]), "+f"(d[3])
        : "r"(a[0]), "r"(a[1]), "r"(a[2]), "r"(a[3]), "r"(b0), "r"(b1));
}

// ---------------- precompute theta/slopes ----------------
__global__ void precomp_kernel(const float* __restrict__ theta_raw,
                               const float* __restrict__ decay_slopes) {
    int i = threadIdx.x;
    if (i < 768) g_theta[i] = softplus_f(theta_raw[i]) + 0.001f;
    if (i < KK)  g_slope[i] = softplus_f(decay_slopes[i]);
}

// ---------------- pack + transpose weights to [N,K] K-major ----------------
__global__ void pack_wcatT_kernel(const float* __restrict__ Wmem, const float* __restrict__ Wq,
                                  const float* __restrict__ Wg, const float* __restrict__ Wdown) {
    int idx = blockIdx.x * 256 + threadIdx.x;   // idx = c*768 + r
    if (idx >= PW * DD) return;
    int c = idx / DD, r = idx % DD;
    float v;
    if (c < OFF_Q)      v = Wmem[r * 780 + c];
    else if (c < OFF_G) v = Wq[r * 768 + (c - OFF_Q)];
    else if (c < OFF_D) v = Wg[r * KK + (c - OFF_G)];
    else                v = Wdown[r * LAT + (c - OFF_D)];
    g_wcatT[idx] = v;
}
__global__ void transpose_kernel(const float* __restrict__ W, float* __restrict__ WT,
                                 int Kd, int N) {
    int idx = blockIdx.x * 256 + threadIdx.x;   // idx = n*Kd + k
    if (idx >= Kd * N) return;
    int n = idx / Kd, k = idx % Kd;
    WT[idx] = W[(size_t)k * N + n];
}

// ---------------- tf32 mma.sync GEMM: C[M,N] = A[M,K] @ Bt[N,K]^T ----------------
// Block 128x128, 8 warps (4 row x 2 col), warp tile 32x64, kchunk 32.
// Smem: XOR-swizzled (seg ^ (row&7)), double buffered: 2*(16K+16K) = 64 KB dynamic.
#define GEMM_SMEM 65536
__global__ __launch_bounds__(256, 2)
void tf32_mma_gemm(const float* __restrict__ A, const float* __restrict__ Bt,
                   float* __restrict__ C, int Ntot, int Kd, int lda, int ldc) {
    extern __shared__ char sm[];
    const uint32_t sbase = smem_u32(sm);
    const int tid = threadIdx.x;
    const int w = tid >> 5;
    const int l = tid & 31;
    const int rowBase = blockIdx.y * 128;
    const int colBase = blockIdx.x * 128;
    const int warpRow = w >> 1;      // 0..3
    const int warpCol = w & 1;       // 0..1

    float acc[2][8][4];
#pragma unroll
    for (int mt = 0; mt < 2; mt++)
#pragma unroll
        for (int nt = 0; nt < 8; nt++)
#pragma unroll
            for (int i = 0; i < 4; i++) acc[mt][nt][i] = 0.f;

    // loader geometry: per iter, warp covers 4 rows x 128B; lanes 0-7 one row.
    const int lr4 = w * 4 + (l >> 3);        // row within 32-row group
    const int lcs = (l & 7) * 16;            // byte seg in row

    // stage tile (ci) into buffer buf from prefetched regs
    float4 pa[4], pb[4];
    auto prefetch = [&](int ci) {
#pragma unroll
        for (int it = 0; it < 4; it++) {
            int r = it * 32 + lr4;
            pa[it] = *(const float4*)(A + (size_t)(rowBase + r) * lda + ci * 32 + (lcs >> 2));
            int n = colBase + r;
            pb[it] = (n < Ntot) ? *(const float4*)(Bt + (size_t)n * Kd + ci * 32 + (lcs >> 2))
                                : make_float4(0.f, 0.f, 0.f, 0.f);
        }
    };
    auto stage = [&](int buf) {
        char* aBuf = sm + buf * 32768;
        char* bBuf = aBuf + 16384;
#pragma unroll
        for (int it = 0; it < 4; it++) {
            int r = it * 32 + lr4;
            int sw = r * 128 + (lcs ^ ((r & 7) << 4));
            *(uint4*)(aBuf + sw) = make_uint4(cvt_tf32(pa[it].x), cvt_tf32(pa[it].y),
                                              cvt_tf32(pa[it].z), cvt_tf32(pa[it].w));
            *(uint4*)(bBuf + sw) = make_uint4(cvt_tf32(pb[it].x), cvt_tf32(pb[it].y),
                                              cvt_tf32(pb[it].z), cvt_tf32(pb[it].w));
        }
    };

    // fragment lane geometry (ldmatrix x4: lanes 0-7 mat0, 8-15 mat1, 16-23 mat2, 24-31 mat3)
    const int lfr = (l & 7) + ((l >> 3) & 1) * 8;   // row within 16-row tile
    const int lf16 = (l >> 4) * 16;                 // byte half of the k8 (32B)

    auto compute = [&](int buf) {
        const uint32_t aB = sbase + buf * 32768;
        const uint32_t bB = aB + 16384;
#pragma unroll
        for (int ks = 0; ks < 4; ks++) {
            const int cb = ks * 32 + lf16;
            uint32_t af[2][4];
#pragma unroll
            for (int mt = 0; mt < 2; mt++) {
                int r = warpRow * 32 + mt * 16 + lfr;
                ldsm4(af[mt], aB + r * 128 + (cb ^ ((r & 7) << 4)));
            }
#pragma unroll
            for (int h = 0; h < 2; h++) {
                uint32_t bf[2][4];
#pragma unroll
                for (int j = 0; j < 2; j++) {
                    int nb = h * 2 + j;
                    int r = warpCol * 64 + nb * 16 + lfr;
                    ldsm4(bf[j], bB + r * 128 + (cb ^ ((r & 7) << 4)));
                }
#pragma unroll
                for (int mt = 0; mt < 2; mt++)
#pragma unroll
                    for (int j = 0; j < 2; j++) {
                        int nt = (h * 2 + j) * 2;
                        mma_tf32(acc[mt][nt],     af[mt], bf[j][0], bf[j][2]);
                        mma_tf32(acc[mt][nt + 1], af[mt], bf[j][1], bf[j][3]);
                    }
            }
        }
    };

    prefetch(0);
    stage(0);
    __syncthreads();

    const int nc = Kd >> 5;
    for (int ci = 0; ci < nc; ci++) {
        const bool more = (ci + 1 < nc);
        if (more) prefetch(ci + 1);
        compute(ci & 1);
        if (more) {
            stage((ci + 1) & 1);
            __syncthreads();
        }
    }

    // epilogue: c0,c1 -> (row g, cols 2tig,2tig+1); c2,c3 -> row g+8
    const int g = l >> 2, tig = l & 3;
#pragma unroll
    for (int mt = 0; mt < 2; mt++)
#pragma unroll
        for (int i = 0; i < 2; i++) {
            int r = rowBase + warpRow * 32 + mt * 16 + g + i * 8;
            float* Crow = C + (size_t)r * ldc;
#pragma unroll
            for (int nt = 0; nt < 8; nt++) {
                int cc = colBase + warpCol * 64 + nt * 8 + tig * 2;
                if (cc < Ntot)
                    *(float2*)(Crow + cc) = make_float2(acc[mt][nt][i * 2], acc[mt][nt][i * 2 + 1]);
            }
        }
}

// ---------------- conv + merged construction ----------------
__global__ __launch_bounds__(256)
void build_merged_kernel(const float* __restrict__ ck,
                         const float* __restrict__ score_scale) {
    const int t = blockIdx.x;
    const int l = t & (LLEN - 1);
    const int tid = threadIdx.x;
    __shared__ float spw[KK];
    const int tb = t * CHN;

    if (tid < KK) {
        float s = 0.f;
#pragma unroll
        for (int i = 0; i < CKN; i++) {
            int ll = l - (CKN - 1) + i;
            if (ll >= 0)
                s += g_zq[(size_t)(t - (CKN - 1) + i) * PW + MEM + tid] * ck[i * 780 + MEM + tid];
        }
        float lp = fminf(fmaxf(score_scale[tid] * s, -20.f), 20.f);
        float pw = expf(lp - g_slope[tid] * (float)(LLEN - 1 - l));
        spw[tid] = pw;
        g_merged[tb + tid] = pw;
    }
    __syncthreads();

    for (int c = tid; c < 768; c += 256) {
        float kv = 0.f;
#pragma unroll
        for (int i = 0; i < CKN; i++) {
            int ll = l - (CKN - 1) + i;
            if (ll >= 0)
                kv += g_zq[(size_t)(t - (CKN - 1) + i) * PW + c] * ck[i * 780 + c];
        }
        float phi = tanhf(kv) * g_theta[c];
        float sn, cn;
        sincosf(phi, &sn, &cn);
        float w = kv * spw[c >> 6];
        g_merged[tb + KK + c] = w * cn;
        g_merged[tb + KK + FLAT + c] = w * sn;
    }
}

// ---------------- blocked cumsum over L (3 passes, in-place) ----------------
__global__ void scan_pass1() {
    int idx = blockIdx.x * 256 + threadIdx.x;
    if (idx >= BB * NCH * CHN) return;
    int c = idx % CHN;
    int r = idx / CHN;
    int ch = r % NCH;
    int b = r / NCH;
    size_t base = ((size_t)b * LLEN + (size_t)ch * CLEN) * CHN + c;
    float s = 0.f;
#pragma unroll 4
    for (int i = 0; i < CLEN; i++) s += g_merged[base + (size_t)i * CHN];
    g_part[(b * CHN + c) * NCH + ch] = s;
}
__global__ void scan_pass2() {
    int idx = blockIdx.x * 256 + threadIdx.x;
    if (idx >= BB * CHN) return;
    int base = idx * NCH;
    float off = 0.f;
#pragma unroll
    for (int i = 0; i < NCH; i++) {
        float v = g_part[base + i];
        g_part[base + i] = off;
        off += v;
    }
}
__global__ void scan_pass3() {
    int idx = blockIdx.x * 256 + threadIdx.x;
    if (idx >= BB * NCH * CHN) return;
    int c = idx % CHN;
    int r = idx / CHN;
    int ch = r % NCH;
    int b = r / NCH;
    size_t base = ((size_t)b * LLEN + (size_t)ch * CLEN) * CHN + c;
    float run = g_part[(b * CHN + c) * NCH + ch];
    for (int i = 0; i < CLEN; i++) {
        size_t a = base + (size_t)i * CHN;
        run += g_merged[a];
        g_merged[a] = run;
    }
}

// ---------------- attention combine: cs + q -> o ----------------
__global__ __launch_bounds__(256)
void combine_q_kernel(const float* __restrict__ norm_scale) {
    const int t = blockIdx.x;
    const int tid = threadIdx.x;
    __shared__ float inv[KK];
    const int tb = t * CHN;
    if (tid < KK) {
        float d = g_merged[tb + tid];
        inv[tid] = 1.f / fmaxf(d, 1e-4f);
    }
    __syncthreads();
    for (int c = tid; c < 768; c += 256) {
        int k = c >> 6, h = c & 63, kq = k >> 1;
        float iv = inv[k];
        float sre = g_merged[tb + KK + c] * iv;
        float sim = g_merged[tb + KK + FLAT + c] * iv;
        float qre = g_zq[(size_t)t * PW + OFF_Q + kq * 128 + 2 * h];
        float qim = g_zq[(size_t)t * PW + OFF_Q + kq * 128 + 2 * h + 1];
        float ns = norm_scale[c];
        g_o[(size_t)t * 1536 + k * 128 + h]      = (sre * qre + sim * qim) * ns;
        g_o[(size_t)t * 1536 + k * 128 + 64 + h] = (sim * qre - sre * qim) * ns;
    }
}

// ---------------- block-diagonal spec GEMM (fp32), fused gate + highway ----------------
__global__ __launch_bounds__(256, 2)
void spec_gemm_kernel(const float* __restrict__ Wre, const float* __restrict__ Wim,
                      const float* __restrict__ bg, const float* __restrict__ hw) {
    const int z = blockIdx.z;
    __shared__ float As[2][8][128];
    __shared__ float Bs[2][8][128];
    const int tid = threadIdx.x;
    const int tx = tid & 15;
    const int ty = tid >> 4;
    const int rowBase = blockIdx.y * 128;
    const int colBase = blockIdx.x * 128;

    const int arow = tid >> 1;
    const int acol = (tid & 1) << 2;
    const int brow = tid >> 5;
    const int bcol = (tid & 31) << 2;

    float acc[8][8];
#pragma unroll
    for (int i = 0; i < 8; i++)
#pragma unroll
        for (int j = 0; j < 8; j++) acc[i][j] = 0.f;

    const float* Ap = g_o + (size_t)(rowBase + arow) * 1536 + z * 128 + acol;
    const float* WreZ = Wre + (size_t)z * 64 * DSW + colBase + bcol;
    const float* WimZ = Wim + (size_t)z * 64 * DSW + colBase + bcol;

    {
        float4 av = *(const float4*)(Ap);
        float4 bv = *(const float4*)(WreZ + (size_t)brow * DSW);
        As[0][acol + 0][arow] = av.x;
        As[0][acol + 1][arow] = av.y;
        As[0][acol + 2][arow] = av.z;
        As[0][acol + 3][arow] = av.w;
        *(float4*)&Bs[0][brow][bcol] = bv;
    }
    __syncthreads();

    const int nIter = 16;
    for (int it = 0; it < nIter; it++) {
        const int buf = it & 1;
        float4 an, bn;
        const bool more = (it + 1 < nIter);
        if (more) {
            int k1 = (it + 1) << 3;
            an = *(const float4*)(Ap + k1);
            int rr = k1 + brow;
            const float* Bp = (rr < 64) ? (WreZ + (size_t)rr * DSW)
                                        : (WimZ + (size_t)(rr - 64) * DSW);
            bn = *(const float4*)(Bp);
        }
#pragma unroll
        for (int kk = 0; kk < 8; kk++) {
            float ar[8], br[8];
            *(float4*)&ar[0] = *(const float4*)&As[buf][kk][ty * 4];
            *(float4*)&ar[4] = *(const float4*)&As[buf][kk][64 + ty * 4];
            *(float4*)&br[0] = *(const float4*)&Bs[buf][kk][tx * 4];
            *(float4*)&br[4] = *(const float4*)&Bs[buf][kk][64 + tx * 4];
#pragma unroll
            for (int i = 0; i < 8; i++)
#pragma unroll
                for (int j = 0; j < 8; j++) acc[i][j] += ar[i] * br[j];
        }
        if (more) {
            const int nb = buf ^ 1;
            As[nb][acol + 0][arow] = an.x;
            As[nb][acol + 1][arow] = an.y;
            As[nb][acol + 2][arow] = an.z;
            As[nb][acol + 3][arow] = an.w;
            *(float4*)&Bs[nb][brow][bcol] = bn;
            __syncthreads();
        }
    }

    const float hwz = hw[z];
    const float bgz = bg[z];
#pragma unroll
    for (int h = 0; h < 2; h++)
#pragma unroll
        for (int i = 0; i < 4; i++) {
            int r = rowBase + h * 64 + ty * 4 + i;
            float gate = sigmoid_f(g_zq[(size_t)r * PW + OFF_G + z] + bgz);
            float* Drow = g_ydir + (size_t)r * 4608 + z * DSW;
#pragma unroll
            for (int jh = 0; jh < 2; jh++) {
                int cc = colBase + jh * 64 + tx * 4;
                float4 dv = *(float4*)(Drow + cc);
                float4 v;
                v.x = acc[h * 4 + i][jh * 4 + 0] * gate + dv.x * hwz;
                v.y = acc[h * 4 + i][jh * 4 + 1] * gate + dv.y * hwz;
                v.z = acc[h * 4 + i][jh * 4 + 2] * gate + dv.z * hwz;
                v.w = acc[h * 4 + i][jh * 4 + 3] * gate + dv.w * hwz;
                *(float4*)(Drow + cc) = v;
            }
        }
}

// ---------------- SiLU-gated combine -> ya (vectorized) ----------------
__global__ void combine_h_kernel() {
    int idx4 = blockIdx.x * 256 + threadIdx.x;
    if (idx4 >= TOK * 2304 / 4) return;
    int idx = idx4 * 4;
    int j = idx % DEXP;
    int k = (idx / DEXP) % KK;
    int t = idx / 2304;
    const float* base = g_ydir + (size_t)t * 4608 + k * DSW + j;
    float4 yv = *(const float4*)(base);
    float4 yg = *(const float4*)(base + DEXP);
    float4 r;
    r.x = yv.x * yg.x * sigmoid_f(yg.x);
    r.y = yv.y * yg.y * sigmoid_f(yg.y);
    r.z = yv.z * yg.z * sigmoid_f(yg.z);
    r.w = yv.w * yg.w * sigmoid_f(yg.w);
    *(float4*)(g_ya + idx) = r;
}

// ---------------- host ----------------
static float* sym_addr(const void* sym) {
    void* p = nullptr;
    cudaGetSymbolAddress(&p, sym);
    return (float*)p;
}

extern "C" void kernel_launch(void* const* d_in, const int* in_sizes, int n_in,
                              void* d_out, int out_size) {
    const float* x        = (const float*)d_in[0];
    const float* W_mem    = (const float*)d_in[1];
    const float* conv_k   = (const float*)d_in[2];
    const float* W_q      = (const float*)d_in[3];
    const float* th_raw   = (const float*)d_in[4];
    const float* d_slopes = (const float*)d_in[5];
    const float* sc_scale = (const float*)d_in[6];
    const float* W_re     = (const float*)d_in[7];
    const float* W_im     = (const float*)d_in[8];
    const float* n_scale  = (const float*)d_in[9];
    const float* Wg       = (const float*)d_in[10];
    const float* bg       = (const float*)d_in[11];
    const float* W_down   = (const float*)d_in[12];
    const float* W_up     = (const float*)d_in[13];
    const float* hw       = (const float*)d_in[14];
    const float* W_out    = (const float*)d_in[15];
    float* out = (float*)d_out;

    float* pwcatT = sym_addr(g_wcatT);
    float* pwupT  = sym_addr(g_wupT);
    float* pwoutT = sym_addr(g_woutT);
    float* pzq    = sym_addr(g_zq);
    float* pydir  = sym_addr(g_ydir);
    float* pya    = sym_addr(g_ya);

    static int smem_set = 0;
    if (!smem_set) {
        cudaFuncSetAttribute(tf32_mma_gemm, cudaFuncAttributeMaxDynamicSharedMemorySize, GEMM_SMEM);
        smem_set = 1;
    }

    dim3 blk(256);
    const int MB = TOK / 128;   // 128 row-blocks

    precomp_kernel<<<1, 768>>>(th_raw, d_slopes);
    pack_wcatT_kernel<<<(PW * DD + 255) / 256, blk>>>(W_mem, W_q, Wg, W_down);
    transpose_kernel<<<(4608 * LAT + 255) / 256, blk>>>(W_up, pwupT, LAT, 4608);
    transpose_kernel<<<(DD * 2304 + 255) / 256, blk>>>(W_out, pwoutT, 2304, DD);

    // fused projection GEMM: x[16384,768] @ WcatT[1752,768]^T -> zq
    tf32_mma_gemm<<<dim3(14, MB), blk, GEMM_SMEM>>>(x, pwcatT, pzq, PW, DD, DD, PW);

    // W_up GEMM: zq_lat[16384,192] @ WupT[4608,192]^T -> ydir
    tf32_mma_gemm<<<dim3(36, MB), blk, GEMM_SMEM>>>(pzq + OFF_D, pwupT, pydir, 4608, LAT, PW, 4608);

    // merged construction + cumsum
    build_merged_kernel<<<TOK, blk>>>(conv_k, sc_scale);
    {
        int n1 = BB * NCH * CHN;
        scan_pass1<<<(n1 + 255) / 256, blk>>>();
        int n2 = BB * CHN;
        scan_pass2<<<(n2 + 255) / 256, blk>>>();
        scan_pass3<<<(n1 + 255) / 256, blk>>>();
    }

    // attention combine + spec GEMM (fused gate+highway into ydir)
    combine_q_kernel<<<TOK, blk>>>(n_scale);
    spec_gemm_kernel<<<dim3(3, MB, KK), blk>>>(W_re, W_im, bg, hw);

    // activation + final projection
    {
        int nh = TOK * 2304 / 4;
        combine_h_kernel<<<(nh + 255) / 256, blk>>>();
    }
    tf32_mma_gemm<<<dim3(6, MB), blk, GEMM_SMEM>>>(pya, pwoutT, out, DD, 2304, 2304, DD);
}